// round 1
// baseline (speedup 1.0000x reference)
#include <cuda_runtime.h>
#include <cstdint>

// ---------------------------------------------------------------------------
// ConvCapsuleLayer3D: 3D conv (shared across input capsules) + sigmoid routing
//   x: (2,4,16,32,32,32) f32   W: (256,16,3,3,3) f32   b: (8,32,1,1,1) f32
//   out: (2,8,32,32,32,32) f32
// Kernel 1: conv -> votes scratch, layout [b][p][ic][oc]  (oc innermost)
// Kernel 2: fused 3-iteration routing, one warp per spatial position
// ---------------------------------------------------------------------------

#define SPATIAL   32
#define NPOS      32768          // 32^3
#define ICAPS     4
#define IA        16
#define NC        8
#define NA        32
#define OC        256            // NC*NA
#define KVOL      432            // IA*27

// conv tiling
#define TZ 4
#define TY 8
#define TX 8
#define TILE_POS 256             // TZ*TY*TX
#define OCT 64                   // oc per block
#define WPAD 66                  // padded oc-row stride in weight smem (even, ~conflict-free)
#define SX_ELEMS (IA * 6 * 10 * 10)          // 9600
#define SW_ELEMS (KVOL * WPAD)               // 28512
#define CONV_SMEM_BYTES ((SX_ELEMS + SW_ELEMS) * 4)

__device__ float g_votes[2 * NPOS * ICAPS * OC];   // 268 MB scratch

// ---- packed fp32x2 helpers -------------------------------------------------
__device__ __forceinline__ unsigned long long pack2(float a, float b) {
    unsigned long long r;
    asm("mov.b64 %0, {%1, %2};" : "=l"(r) : "f"(a), "f"(b));
    return r;
}
__device__ __forceinline__ void unpack2(unsigned long long v, float& a, float& b) {
    asm("mov.b64 {%0, %1}, %2;" : "=f"(a), "=f"(b) : "l"(v));
}
__device__ __forceinline__ void fma2(unsigned long long& d,
                                     unsigned long long a, unsigned long long b) {
    asm("fma.rn.f32x2 %0, %1, %2, %0;" : "+l"(d) : "l"(a), "l"(b));
}

// ---------------------------------------------------------------------------
// Kernel 1: conv. grid (128 spatial tiles, 8 conv-batches, 4 oc-tiles), 256 thr
// ---------------------------------------------------------------------------
__global__ void __launch_bounds__(256, 1)
conv_kernel(const float* __restrict__ X, const float* __restrict__ W) {
    extern __shared__ float smem[];
    float* sx  = smem;               // [ci][z(6)][y(10)][x(10)]
    float* swT = smem + SX_ELEMS;    // [k(432)][oc(64) padded to 66]

    const int tid    = threadIdx.x;
    const int tile   = blockIdx.x;           // 0..127
    const int nb     = blockIdx.y;           // 0..7  (= b*4 + ic)
    const int octile = blockIdx.z;           // 0..3

    const int tz = tile >> 4, ty = (tile >> 2) & 3, tx = tile & 3;
    const int oz = tz * TZ, oy = ty * TY, ox = tx * TX;

    // --- stage input tile with halo (zero-padded) ---
    for (int i = tid; i < SX_ELEMS; i += 256) {
        int ci = i / 600;
        int r  = i - ci * 600;
        int zz = r / 100;  r -= zz * 100;
        int yy = r / 10;
        int xx = r - yy * 10;
        int gz = oz + zz - 1, gy = oy + yy - 1, gx = ox + xx - 1;
        float v = 0.f;
        if ((unsigned)gz < 32u && (unsigned)gy < 32u && (unsigned)gx < 32u)
            v = X[((nb * IA + ci) << 15) + (gz << 10) + (gy << 5) + gx];
        sx[i] = v;
    }
    // --- stage weights transposed: swT[k][ol] ---
    const float* Wg = W + octile * (OCT * KVOL);
    for (int i = tid; i < OCT * KVOL; i += 256) {
        int ol = i / KVOL;
        int k  = i - ol * KVOL;
        swT[k * WPAD + ol] = Wg[i];
    }
    __syncthreads();

    // --- compute: thread = (og, pid); 4 positions along x, 16 oc (8 pairs) ---
    const int og  = tid >> 6;            // 0..3  -> oc group of 16
    const int pid = tid & 63;
    const int xh  = pid & 1;             // x half (0 or 4)
    const int y   = (pid >> 1) & 7;
    const int z   = pid >> 4;            // 0..3
    const int xoff = xh * 4;

    unsigned long long acc[4][8];
    #pragma unroll
    for (int i = 0; i < 4; ++i)
        #pragma unroll
        for (int j = 0; j < 8; ++j) acc[i][j] = 0ull;

    const float* xbase = sx + z * 100 + y * 10 + xoff;
    const float* wob   = swT + og * 16;

    #pragma unroll 1
    for (int ci = 0; ci < IA; ++ci) {
        #pragma unroll 1
        for (int kd = 0; kd < 3; ++kd) {
            const float* xp = xbase + ci * 600 + kd * 100;
            const float* wb = wob + (ci * 9 + kd * 3) * (3 * WPAD);
            #pragma unroll
            for (int kh = 0; kh < 3; ++kh) {
                const float* xr = xp + kh * 10;
                unsigned long long xd[6];
                #pragma unroll
                for (int j = 0; j < 6; ++j) { float a = xr[j]; xd[j] = pack2(a, a); }
                const float* wk = wb + kh * 3 * WPAD;
                #pragma unroll
                for (int kw = 0; kw < 3; ++kw) {
                    const unsigned long long* w2p =
                        reinterpret_cast<const unsigned long long*>(wk + kw * WPAD);
                    #pragma unroll
                    for (int pp = 0; pp < 8; ++pp) {
                        unsigned long long w2 = w2p[pp];   // broadcast LDS.64
                        fma2(acc[0][pp], xd[kw + 0], w2);
                        fma2(acc[1][pp], xd[kw + 1], w2);
                        fma2(acc[2][pp], xd[kw + 2], w2);
                        fma2(acc[3][pp], xd[kw + 3], w2);
                    }
                }
            }
        }
    }

    // --- epilogue: votes[b][p][ic][oc], 16 consecutive floats per position ---
    const int b_  = nb >> 2;
    const int ic_ = nb & 3;
    const int gz0 = oz + z, gy0 = oy + y, gx0 = ox + xoff;
    #pragma unroll
    for (int i = 0; i < 4; ++i) {
        int gp = (gz0 << 10) + (gy0 << 5) + gx0 + i;
        float* dst = g_votes
                   + ((size_t)((b_ << 15) + gp) * ICAPS + ic_) * OC
                   + (octile << 6) + (og << 4);
        float4 o;
        float a0,a1,b0,b1;
        unpack2(acc[i][0], a0, a1); unpack2(acc[i][1], b0, b1);
        o = make_float4(a0, a1, b0, b1); reinterpret_cast<float4*>(dst)[0] = o;
        unpack2(acc[i][2], a0, a1); unpack2(acc[i][3], b0, b1);
        o = make_float4(a0, a1, b0, b1); reinterpret_cast<float4*>(dst)[1] = o;
        unpack2(acc[i][4], a0, a1); unpack2(acc[i][5], b0, b1);
        o = make_float4(a0, a1, b0, b1); reinterpret_cast<float4*>(dst)[2] = o;
        unpack2(acc[i][6], a0, a1); unpack2(acc[i][7], b0, b1);
        o = make_float4(a0, a1, b0, b1); reinterpret_cast<float4*>(dst)[3] = o;
    }
}

// ---------------------------------------------------------------------------
// Kernel 2: routing. 512 threads = 16 warps; warp = one spatial position,
// lane = atom (NA == 32). 3 iterations fully in registers.
// ---------------------------------------------------------------------------
__device__ __forceinline__ float warp_sum(float v) {
    #pragma unroll
    for (int o = 16; o > 0; o >>= 1) v += __shfl_xor_sync(0xFFFFFFFFu, v, o);
    return v;
}

__global__ void __launch_bounds__(512, 1)
routing_kernel(const float* __restrict__ bias, float* __restrict__ out) {
    __shared__ float s[OC][17];          // [nc*32+na][16 positions], padded

    const int lane = threadIdx.x & 31;
    const int warp = threadIdx.x >> 5;   // 0..15
    const int blk  = blockIdx.x;         // 0..4095
    const int b    = blk >> 11;          // 2048 blocks per batch
    const int p0   = (blk & 2047) * 16;
    const int p    = p0 + warp;

    // load votes: v[ic][nc] for this lane's atom
    float v[ICAPS][NC];
    const float* vb = g_votes + ((size_t)((b << 15) + p) * ICAPS) * OC + lane;
    #pragma unroll
    for (int ic = 0; ic < ICAPS; ++ic)
        #pragma unroll
        for (int nc = 0; nc < NC; ++nc)
            v[ic][nc] = vb[ic * OC + nc * 32];

    float bb[NC];
    #pragma unroll
    for (int nc = 0; nc < NC; ++nc) bb[nc] = bias[nc * 32 + lane];

    float lgt[ICAPS][NC];
    #pragma unroll
    for (int ic = 0; ic < ICAPS; ++ic)
        #pragma unroll
        for (int nc = 0; nc < NC; ++nc) lgt[ic][nc] = 1.0f;

    float act[NC];
    #pragma unroll
    for (int it = 0; it < 3; ++it) {
        #pragma unroll
        for (int nc = 0; nc < NC; ++nc) {
            float pre = bb[nc];
            #pragma unroll
            for (int ic = 0; ic < ICAPS; ++ic) {
                float route = 1.0f / (1.0f + __expf(-lgt[ic][nc]));
                pre = fmaf(route, v[ic][nc], pre);
            }
            float sq = warp_sum(pre * pre);
            float scale = sq / ((1.0f + sq) * sqrtf(sq + 1e-9f));
            act[nc] = pre * scale;
        }
        if (it < 2) {
            #pragma unroll
            for (int ic = 0; ic < ICAPS; ++ic)
                #pragma unroll
                for (int nc = 0; nc < NC; ++nc)
                    lgt[ic][nc] += warp_sum(v[ic][nc] * act[nc]);
        }
    }

    // stage to smem for coalesced output (out[b][nc][na][p])
    #pragma unroll
    for (int nc = 0; nc < NC; ++nc) s[nc * 32 + lane][warp] = act[nc];
    __syncthreads();

    const int c   = threadIdx.x & 15;      // position within block
    const int rw  = threadIdx.x >> 4;      // 32 rows per pass
    #pragma unroll
    for (int rr = 0; rr < 8; ++rr) {
        int row = rr * 32 + rw;            // (nc*32+na)
        out[((size_t)(b * OC + row) << 15) + p0 + c] = s[row][c];
    }
}

// ---------------------------------------------------------------------------
extern "C" void kernel_launch(void* const* d_in, const int* in_sizes, int n_in,
                              void* d_out, int out_size) {
    const float* x = (const float*)d_in[0];   // (2,4,16,32,32,32)
    const float* W = (const float*)d_in[1];   // (256,16,3,3,3)
    const float* b = (const float*)d_in[2];   // (8,32,1,1,1)
    float* out = (float*)d_out;

    cudaFuncSetAttribute(conv_kernel,
                         cudaFuncAttributeMaxDynamicSharedMemorySize,
                         CONV_SMEM_BYTES);

    dim3 cgrid(128, 8, 4);
    conv_kernel<<<cgrid, 256, CONV_SMEM_BYTES>>>(x, W);
    routing_kernel<<<4096, 512>>>(b, out);
}

// round 3
// speedup vs baseline: 2.7570x; 2.7570x over previous
#include <cuda_runtime.h>
#include <cstdint>

// ---------------------------------------------------------------------------
// ConvCapsuleLayer3D via mma.sync tf32 (sm_100 baseline PTX, no tcgen05):
//   pad_kernel   : x -> g_xpad [128ch][34^3], values pre-rounded to tf32
//   wfrag_kernel : W -> g_wfrag, m16n8k8 A-fragment order, tf32 bit patterns
//   conv_mma     : implicit GEMM votes[oc,pos] = W[oc,k] * im2col[k,pos]
//                  CTA 128x128, K=432 in 27 chunks of 16, cp.async 2-stage
//   routing      : fused 3-iter sigmoid routing, low-shfl lane mapping
// ---------------------------------------------------------------------------

#define KTOT 432
#define NCH  27
#define PADC 39304      // 34^3
#define PADZ 1156
#define PADY 34
#define BST  132        // padded B smem row stride (floats)

__device__ float    g_votes[2 * 32768 * 1024];        // 268 MB
__device__ float    g_xpad[128 * PADC];               // 20 MB
__device__ uint32_t g_wfrag[54 * 16 * 32 * 4];        // 432 KB

// smem (floats): [0..447] int tbl(432) ; [448..] bufs 2x2112 / epilogue 16896
#define SM_BUF      448
#define SMEM_FLOATS (448 + 128 * BST)
#define SMEM_BYTES  (SMEM_FLOATS * 4)

static __device__ __forceinline__ uint32_t cvt_tf32(float f) {
    uint32_t u;
    asm("cvt.rna.tf32.f32 %0, %1;" : "=r"(u) : "f"(f));
    return u;
}

// ---------------------------------------------------------------------------
__global__ void pad_kernel(const float* __restrict__ X) {
    int idx = blockIdx.x * 256 + threadIdx.x;
    if (idx >= 128 * PADC) return;
    int ch = idx / PADC;
    int r  = idx - ch * PADC;
    int zp = r / PADZ;  r -= zp * PADZ;
    int yp = r / PADY;
    int xp = r - yp * PADY;
    int z = zp - 1, y = yp - 1, x = xp - 1;
    float v = 0.f;
    if ((unsigned)z < 32u && (unsigned)y < 32u && (unsigned)x < 32u)
        v = X[(ch << 15) + (z << 10) + (y << 5) + x];
    g_xpad[idx] = __uint_as_float(cvt_tf32(v));
}

// Wfrag[i], i = ((ks*16 + m16)*32 + lane)*4 + j
__global__ void wfrag_kernel(const float* __restrict__ W) {
    int i = blockIdx.x * 256 + threadIdx.x;
    if (i >= 54 * 16 * 32 * 4) return;
    int j    = i & 3;
    int lane = (i >> 2) & 31;
    int m16  = (i >> 7) & 15;
    int ks   = i >> 11;
    int gid = lane >> 2, tig = lane & 3;
    int m = m16 * 16 + gid + ((j & 1) ? 8 : 0);
    int k = ks * 8 + tig + ((j >= 2) ? 4 : 0);
    g_wfrag[i] = cvt_tf32(W[m * KTOT + k]);
}

// ---------------------------------------------------------------------------
// conv: grid (256 pos-tiles, 8 nb, 2 mtiles), 256 threads, 2 CTAs/SM
// ---------------------------------------------------------------------------
__global__ void __launch_bounds__(256, 2)
conv_mma_kernel() {
    extern __shared__ float sm[];
    int* tbl = (int*)sm;

    const int tid  = threadIdx.x;
    const int w    = tid >> 5, lane = tid & 31;
    const int gid  = lane >> 2, tig = lane & 3;
    const int wm   = w >> 2,   wn  = w & 3;

    const int bx = blockIdx.x;            // 0..255
    const int nb = blockIdx.y;            // 0..7 = b*4+ic
    const int mt = blockIdx.z;            // 0..1
    const int z  = bx >> 3, y0 = (bx & 7) * 4;

    for (int k = tid; k < KTOT; k += 256) {
        int ci = k / 27;  int r = k - ci * 27;
        int kd = r / 9;   r -= kd * 9;
        int kh = r / 3;   int kw = r - kh * 3;
        tbl[k] = ci * PADC + kd * PADZ + kh * PADY + kw;
    }
    __syncthreads();

    // staging: thread -> (n = tid&127, k-half = tid>>7)
    const int sn  = tid & 127;
    const int skh = tid >> 7;
    const float* xb = g_xpad + nb * (16 * PADC) + z * PADZ
                    + (y0 + (sn >> 5)) * PADY + (sn & 31);
    const uint32_t smem_base =
        (uint32_t)__cvta_generic_to_shared(sm + SM_BUF);

    float acc[4][4][4];
    #pragma unroll
    for (int a = 0; a < 4; ++a)
        #pragma unroll
        for (int b = 0; b < 4; ++b)
            #pragma unroll
            for (int c = 0; c < 4; ++c) acc[a][b][c] = 0.f;

    // ---- prologue: stage chunk 0 ----
    {
        #pragma unroll
        for (int j = 0; j < 8; ++j) {
            int k = skh * 8 + j;
            const float* src = xb + tbl[k];
            uint32_t dst = smem_base + (uint32_t)(k * BST + sn) * 4u;
            asm volatile("cp.async.ca.shared.global [%0], [%1], 4;"
                         :: "r"(dst), "l"(src));
        }
        asm volatile("cp.async.commit_group;");
    }

    const uint4* wf = (const uint4*)g_wfrag;

    #pragma unroll 1
    for (int c = 0; c < NCH; ++c) {
        if (c + 1 < NCH) {
            uint32_t base = smem_base + (uint32_t)(((c + 1) & 1) * 2112) * 4u;
            #pragma unroll
            for (int j = 0; j < 8; ++j) {
                int k = skh * 8 + j;
                const float* src = xb + tbl[(c + 1) * 16 + k];
                uint32_t dst = base + (uint32_t)(k * BST + sn) * 4u;
                asm volatile("cp.async.ca.shared.global [%0], [%1], 4;"
                             :: "r"(dst), "l"(src));
            }
            asm volatile("cp.async.commit_group;");
            asm volatile("cp.async.wait_group 1;");
        } else {
            asm volatile("cp.async.wait_group 0;");
        }
        __syncthreads();

        const float* buf = sm + SM_BUF + (c & 1) * 2112;
        #pragma unroll
        for (int ks2 = 0; ks2 < 2; ++ks2) {
            const int ks = c * 2 + ks2;
            uint4 A[4];
            #pragma unroll
            for (int mi = 0; mi < 4; ++mi)
                A[mi] = wf[(ks * 16 + mt * 8 + wm * 4 + mi) * 32 + lane];
            #pragma unroll
            for (int nt = 0; nt < 4; ++nt) {
                const int ncol = wn * 32 + nt * 8 + gid;
                uint32_t b0 = __float_as_uint(buf[(ks2 * 8 + tig) * BST + ncol]);
                uint32_t b1 = __float_as_uint(buf[(ks2 * 8 + tig + 4) * BST + ncol]);
                #pragma unroll
                for (int mi = 0; mi < 4; ++mi) {
                    asm volatile(
                        "mma.sync.aligned.m16n8k8.row.col.f32.tf32.tf32.f32 "
                        "{%0,%1,%2,%3}, {%4,%5,%6,%7}, {%8,%9}, {%0,%1,%2,%3};"
                        : "+f"(acc[mi][nt][0]), "+f"(acc[mi][nt][1]),
                          "+f"(acc[mi][nt][2]), "+f"(acc[mi][nt][3])
                        : "r"(A[mi].x), "r"(A[mi].y), "r"(A[mi].z), "r"(A[mi].w),
                          "r"(b0), "r"(b1));
                }
            }
        }
        __syncthreads();
    }

    // ---- epilogue: transpose via smem, coalesced votes write ----
    float* ep = sm + SM_BUF;   // [128 pos][BST]
    #pragma unroll
    for (int mi = 0; mi < 4; ++mi)
        #pragma unroll
        for (int nt = 0; nt < 4; ++nt) {
            const int oc0  = wm * 64 + mi * 16 + gid;
            const int pos0 = wn * 32 + nt * 8 + tig * 2;
            ep[pos0 * BST + oc0]           = acc[mi][nt][0];
            ep[(pos0 + 1) * BST + oc0]     = acc[mi][nt][1];
            ep[pos0 * BST + oc0 + 8]       = acc[mi][nt][2];
            ep[(pos0 + 1) * BST + oc0 + 8] = acc[mi][nt][3];
        }
    __syncthreads();

    const int b_ = nb >> 2, ic_ = nb & 3;
    #pragma unroll
    for (int i = 0; i < 16; ++i) {
        const int pl = w * 16 + i;
        const int y  = y0 + (pl >> 5);
        const int x  = pl & 31;
        const int p  = (z << 10) | (y << 5) | x;
        float4 v = *(const float4*)(ep + pl * BST + lane * 4);
        *(float4*)(g_votes + ((size_t)((b_ << 15) + p) << 10)
                   + ic_ * 256 + mt * 128 + lane * 4) = v;
    }
}

// ---------------------------------------------------------------------------
// routing: warp = position, lane = (nc = lane>>2, quarter = lane&3),
// each lane owns 8 atoms -> reductions are 8 local FMAs + 2 shfls.
// ---------------------------------------------------------------------------
__global__ void __launch_bounds__(512, 2)
routing_kernel(const float* __restrict__ bias, float* __restrict__ out) {
    __shared__ float s[256][17];

    const int lane = threadIdx.x & 31;
    const int warp = threadIdx.x >> 5;       // 0..15
    const int blk  = blockIdx.x;
    const int b    = blk >> 11;
    const int p0   = (blk & 2047) * 16;
    const int p    = p0 + warp;
    const int nc   = lane >> 2, q = lane & 3;

    const float* vb = g_votes + ((size_t)((b << 15) + p) << 10) + nc * 32 + q * 8;
    float v[4][8];
    #pragma unroll
    for (int ic = 0; ic < 4; ++ic) {
        float4 a = *(const float4*)(vb + ic * 256);
        float4 c = *(const float4*)(vb + ic * 256 + 4);
        v[ic][0] = a.x; v[ic][1] = a.y; v[ic][2] = a.z; v[ic][3] = a.w;
        v[ic][4] = c.x; v[ic][5] = c.y; v[ic][6] = c.z; v[ic][7] = c.w;
    }
    float bb[8];
    {
        float4 a = *(const float4*)(bias + nc * 32 + q * 8);
        float4 c = *(const float4*)(bias + nc * 32 + q * 8 + 4);
        bb[0] = a.x; bb[1] = a.y; bb[2] = a.z; bb[3] = a.w;
        bb[4] = c.x; bb[5] = c.y; bb[6] = c.z; bb[7] = c.w;
    }

    float lgt[4] = {1.f, 1.f, 1.f, 1.f};
    float act[8];

    #pragma unroll
    for (int it = 0; it < 3; ++it) {
        float r[4];
        #pragma unroll
        for (int ic = 0; ic < 4; ++ic)
            r[ic] = 1.0f / (1.0f + __expf(-lgt[ic]));

        float pre[8], sql = 0.f;
        #pragma unroll
        for (int j = 0; j < 8; ++j) {
            float pv = bb[j];
            #pragma unroll
            for (int ic = 0; ic < 4; ++ic) pv = fmaf(r[ic], v[ic][j], pv);
            pre[j] = pv;
            sql = fmaf(pv, pv, sql);
        }
        sql += __shfl_xor_sync(0xFFFFFFFFu, sql, 1);
        sql += __shfl_xor_sync(0xFFFFFFFFu, sql, 2);
        float scale = sql / ((1.0f + sql) * sqrtf(sql + 1e-9f));
        #pragma unroll
        for (int j = 0; j < 8; ++j) act[j] = pre[j] * scale;

        if (it < 2) {
            #pragma unroll
            for (int ic = 0; ic < 4; ++ic) {
                float d = 0.f;
                #pragma unroll
                for (int j = 0; j < 8; ++j) d = fmaf(v[ic][j], act[j], d);
                d += __shfl_xor_sync(0xFFFFFFFFu, d, 1);
                d += __shfl_xor_sync(0xFFFFFFFFu, d, 2);
                lgt[ic] += d;
            }
        }
    }

    #pragma unroll
    for (int j = 0; j < 8; ++j) s[nc * 32 + q * 8 + j][warp] = act[j];
    __syncthreads();

    const int c  = threadIdx.x & 15;
    const int rw = threadIdx.x >> 4;
    #pragma unroll
    for (int rr = 0; rr < 8; ++rr) {
        int row = rr * 32 + rw;
        out[((size_t)(b * 256 + row) << 15) + p0 + c] = s[row][c];
    }
}

// ---------------------------------------------------------------------------
extern "C" void kernel_launch(void* const* d_in, const int* in_sizes, int n_in,
                              void* d_out, int out_size) {
    const float* x = (const float*)d_in[0];
    const float* W = (const float*)d_in[1];
    const float* b = (const float*)d_in[2];
    float* out = (float*)d_out;

    cudaFuncSetAttribute(conv_mma_kernel,
                         cudaFuncAttributeMaxDynamicSharedMemorySize, SMEM_BYTES);

    pad_kernel<<<(128 * PADC + 255) / 256, 256>>>(x);
    wfrag_kernel<<<432, 256>>>(W);
    dim3 cgrid(256, 8, 2);
    conv_mma_kernel<<<cgrid, 256, SMEM_BYTES>>>();
    routing_kernel<<<4096, 512>>>(b, out);
}

// round 4
// speedup vs baseline: 3.7830x; 1.3722x over previous
#include <cuda_runtime.h>
#include <cuda_fp16.h>
#include <cstdint>

// ---------------------------------------------------------------------------
// ConvCapsuleLayer3D via mma.sync tf32 (sm_100 baseline PTX):
//   pad_kernel   : x -> g_xpad [128ch][34^3], pre-rounded to tf32
//   wfrag_kernel : W -> g_wfrag in m16n8k8 A-fragment order (tf32 bits)
//   conv_mma     : implicit GEMM, CTA = 128oc x 256pos, K=432.
//                  Whole input halo (16ch x 3 x 10 x 34 = 65KB) resident in
//                  smem -> mainloop is pure LDG(A,L1) + LDS(B) + HMMA.
//   routing      : fused 3-iter sigmoid routing, fp16 votes
// ---------------------------------------------------------------------------

#define KTOT 432
#define PADC 39304      // 34^3
#define PADZ 1156
#define PADY 34

// halo strides (floats)
#define H_CI 1020       // 3*10*34
#define H_KD 340        // 10*34
#define H_KH 34

__device__ __half    g_votes[2 * 32768 * 1024];       // 134 MB (fp16)
__device__ float     g_xpad[128 * PADC];              // 20 MB
__device__ uint32_t  g_wfrag[54 * 16 * 32 * 4];       // 432 KB

// conv smem: tbl[432] ints then halo[16320] floats
#define SM_HALO     448
#define SMEM_FLOATS (448 + 16320)
#define SMEM_BYTES  (SMEM_FLOATS * 4)

static __device__ __forceinline__ uint32_t cvt_tf32(float f) {
    uint32_t u;
    asm("cvt.rna.tf32.f32 %0, %1;" : "=r"(u) : "f"(f));
    return u;
}

// ---------------------------------------------------------------------------
__global__ void pad_kernel(const float* __restrict__ X) {
    int idx = blockIdx.x * 256 + threadIdx.x;
    if (idx >= 128 * PADC) return;
    int ch = idx / PADC;
    int r  = idx - ch * PADC;
    int zp = r / PADZ;  r -= zp * PADZ;
    int yp = r / PADY;
    int xp = r - yp * PADY;
    int z = zp - 1, y = yp - 1, x = xp - 1;
    float v = 0.f;
    if ((unsigned)z < 32u && (unsigned)y < 32u && (unsigned)x < 32u)
        v = X[(ch << 15) + (z << 10) + (y << 5) + x];
    g_xpad[idx] = __uint_as_float(cvt_tf32(v));
}

// Wfrag[i], i = ((ks*16 + m16)*32 + lane)*4 + j
__global__ void wfrag_kernel(const float* __restrict__ W) {
    int i = blockIdx.x * 256 + threadIdx.x;
    if (i >= 54 * 16 * 32 * 4) return;
    int j    = i & 3;
    int lane = (i >> 2) & 31;
    int m16  = (i >> 7) & 15;
    int ks   = i >> 11;
    int gid = lane >> 2, tig = lane & 3;
    int m = m16 * 16 + gid + ((j & 1) ? 8 : 0);
    int k = ks * 8 + tig + ((j >= 2) ? 4 : 0);
    g_wfrag[i] = cvt_tf32(W[m * KTOT + k]);
}

// ---------------------------------------------------------------------------
// conv: grid (128 [z, y-quarter], 8 [nb], 2 [mt]), 512 threads, 1 CTA/SM
// warp tile: 64 oc x 32 pos ; 16 warps = (wm 2) x (wn 8)
// ---------------------------------------------------------------------------
__global__ void __launch_bounds__(512, 1)
conv_mma_kernel() {
    extern __shared__ float sm[];
    int*   tbl  = (int*)sm;
    float* halo = sm + SM_HALO;

    const int tid  = threadIdx.x;
    const int w    = tid >> 5, lane = tid & 31;
    const int gid  = lane >> 2, tig = lane & 3;
    const int wm   = w >> 3;            // 0..1
    const int wn   = w & 7;             // 0..7

    const int bx = blockIdx.x;          // 0..127
    const int nb = blockIdx.y;          // 0..7 (= b*4 + ic)
    const int mt = blockIdx.z;          // 0..1
    const int z  = bx >> 2, y0 = (bx & 3) * 8;

    // k -> halo-relative offset table
    for (int k = tid; k < KTOT; k += 512) {
        int ci = k / 27;  int r = k - ci * 27;
        int kd = r / 9;   r -= kd * 9;
        int kh = r / 3;   int kw = r - kh * 3;
        tbl[k] = ci * H_CI + kd * H_KD + kh * H_KH + kw;
    }
    // halo load: 16ch x zp[z..z+2] x yp[y0..y0+9] x xp[0..33]
    {
        const float* xsrc = g_xpad + nb * (16 * PADC) + z * PADZ + y0 * PADY;
        for (int i = tid; i < 16320; i += 512) {
            int row = i / 34;
            int x   = i - row * 34;
            int ci  = row / 30;
            int rr  = row - ci * 30;
            int zp  = rr / 10;
            int yp  = rr - zp * 10;
            halo[ci * H_CI + zp * H_KD + yp * H_KH + x] =
                xsrc[ci * PADC + zp * PADZ + yp * PADY + x];
        }
    }
    __syncthreads();

    // per-lane position offsets (4 n-tiles of 8)
    int posoff[4];
    #pragma unroll
    for (int nt = 0; nt < 4; ++nt) {
        int ncol = wn * 32 + nt * 8 + gid;        // 0..255
        posoff[nt] = (ncol >> 5) * H_KH + (ncol & 31);
    }

    float acc[4][4][4];
    #pragma unroll
    for (int a = 0; a < 4; ++a)
        #pragma unroll
        for (int b = 0; b < 4; ++b)
            #pragma unroll
            for (int c = 0; c < 4; ++c) acc[a][b][c] = 0.f;

    // A fragments: ((ks*16 + mt*8 + wm*4 + mi)*32 + lane)
    const uint4* wf = (const uint4*)g_wfrag + (size_t)(mt * 8 + wm * 4) * 32 + lane;

    #pragma unroll 2
    for (int ks = 0; ks < 54; ++ks) {
        const int k0 = tbl[ks * 8 + tig];
        const int k1 = tbl[ks * 8 + tig + 4];
        uint4 A[4];
        #pragma unroll
        for (int mi = 0; mi < 4; ++mi)
            A[mi] = wf[(ks * 16 + mi) * 32];
        #pragma unroll
        for (int nt = 0; nt < 4; ++nt) {
            uint32_t b0 = __float_as_uint(halo[k0 + posoff[nt]]);
            uint32_t b1 = __float_as_uint(halo[k1 + posoff[nt]]);
            #pragma unroll
            for (int mi = 0; mi < 4; ++mi) {
                asm volatile(
                    "mma.sync.aligned.m16n8k8.row.col.f32.tf32.tf32.f32 "
                    "{%0,%1,%2,%3}, {%4,%5,%6,%7}, {%8,%9}, {%0,%1,%2,%3};"
                    : "+f"(acc[mi][nt][0]), "+f"(acc[mi][nt][1]),
                      "+f"(acc[mi][nt][2]), "+f"(acc[mi][nt][3])
                    : "r"(A[mi].x), "r"(A[mi].y), "r"(A[mi].z), "r"(A[mi].w),
                      "r"(b0), "r"(b1));
            }
        }
    }

    // epilogue: fp16 votes[b][p][ic*256+oc], 16B-coalesced half stores
    const int b_ = nb >> 2, ic_ = nb & 3;
    #pragma unroll
    for (int mi = 0; mi < 4; ++mi) {
        const int oc = mt * 128 + wm * 64 + mi * 16 + gid;
        #pragma unroll
        for (int nt = 0; nt < 4; ++nt) {
            const int posl = wn * 32 + nt * 8 + tig * 2;
            const int y = y0 + (posl >> 5);
            const int x = posl & 31;
            const int p = (z << 10) | (y << 5) | x;
            __half* dst = g_votes + (((size_t)((b_ << 15) + p)) << 10)
                        + ic_ * 256 + oc;
            dst[0]        = __float2half_rn(acc[mi][nt][0]);
            dst[8]        = __float2half_rn(acc[mi][nt][2]);
            dst[1024]     = __float2half_rn(acc[mi][nt][1]);
            dst[1024 + 8] = __float2half_rn(acc[mi][nt][3]);
        }
    }
}

// ---------------------------------------------------------------------------
// routing: warp = position, lane = (nc = lane>>2, quarter = lane&3),
// 8 atoms per lane -> reductions = 8 local FMAs + 2 shfls. fp16 votes.
// ---------------------------------------------------------------------------
__global__ void __launch_bounds__(512, 2)
routing_kernel(const float* __restrict__ bias, float* __restrict__ out) {
    __shared__ float s[256][17];

    const int lane = threadIdx.x & 31;
    const int warp = threadIdx.x >> 5;
    const int blk  = blockIdx.x;
    const int b    = blk >> 11;
    const int p0   = (blk & 2047) * 16;
    const int p    = p0 + warp;
    const int nc   = lane >> 2, q = lane & 3;

    const __half* vb = g_votes + (((size_t)((b << 15) + p)) << 10) + nc * 32 + q * 8;
    float v[4][8];
    #pragma unroll
    for (int ic = 0; ic < 4; ++ic) {
        uint4 raw = *(const uint4*)(vb + ic * 256);
        float2 f;
        f = __half22float2(*(__half2*)&raw.x); v[ic][0] = f.x; v[ic][1] = f.y;
        f = __half22float2(*(__half2*)&raw.y); v[ic][2] = f.x; v[ic][3] = f.y;
        f = __half22float2(*(__half2*)&raw.z); v[ic][4] = f.x; v[ic][5] = f.y;
        f = __half22float2(*(__half2*)&raw.w); v[ic][6] = f.x; v[ic][7] = f.y;
    }
    float bb[8];
    {
        float4 a = *(const float4*)(bias + nc * 32 + q * 8);
        float4 c = *(const float4*)(bias + nc * 32 + q * 8 + 4);
        bb[0] = a.x; bb[1] = a.y; bb[2] = a.z; bb[3] = a.w;
        bb[4] = c.x; bb[5] = c.y; bb[6] = c.z; bb[7] = c.w;
    }

    float lgt[4] = {1.f, 1.f, 1.f, 1.f};
    float act[8];

    #pragma unroll
    for (int it = 0; it < 3; ++it) {
        float r[4];
        #pragma unroll
        for (int ic = 0; ic < 4; ++ic)
            r[ic] = 1.0f / (1.0f + __expf(-lgt[ic]));

        float pre[8], sql = 0.f;
        #pragma unroll
        for (int j = 0; j < 8; ++j) {
            float pv = bb[j];
            #pragma unroll
            for (int ic = 0; ic < 4; ++ic) pv = fmaf(r[ic], v[ic][j], pv);
            pre[j] = pv;
            sql = fmaf(pv, pv, sql);
        }
        sql += __shfl_xor_sync(0xFFFFFFFFu, sql, 1);
        sql += __shfl_xor_sync(0xFFFFFFFFu, sql, 2);
        float scale = sql / ((1.0f + sql) * sqrtf(sql + 1e-9f));
        #pragma unroll
        for (int j = 0; j < 8; ++j) act[j] = pre[j] * scale;

        if (it < 2) {
            #pragma unroll
            for (int ic = 0; ic < 4; ++ic) {
                float d = 0.f;
                #pragma unroll
                for (int j = 0; j < 8; ++j) d = fmaf(v[ic][j], act[j], d);
                d += __shfl_xor_sync(0xFFFFFFFFu, d, 1);
                d += __shfl_xor_sync(0xFFFFFFFFu, d, 2);
                lgt[ic] += d;
            }
        }
    }

    #pragma unroll
    for (int j = 0; j < 8; ++j) s[nc * 32 + q * 8 + j][warp] = act[j];
    __syncthreads();

    const int c  = threadIdx.x & 15;
    const int rw = threadIdx.x >> 4;
    #pragma unroll
    for (int rr = 0; rr < 8; ++rr) {
        int row = rr * 32 + rw;
        out[((size_t)(b * 256 + row) << 15) + p0 + c] = s[row][c];
    }
}

// ---------------------------------------------------------------------------
extern "C" void kernel_launch(void* const* d_in, const int* in_sizes, int n_in,
                              void* d_out, int out_size) {
    const float* x = (const float*)d_in[0];
    const float* W = (const float*)d_in[1];
    const float* b = (const float*)d_in[2];
    float* out = (float*)d_out;

    cudaFuncSetAttribute(conv_mma_kernel,
                         cudaFuncAttributeMaxDynamicSharedMemorySize, SMEM_BYTES);

    pad_kernel<<<(128 * PADC + 255) / 256, 256>>>(x);
    wfrag_kernel<<<432, 256>>>(W);
    dim3 cgrid(128, 8, 2);
    conv_mma_kernel<<<cgrid, 512, SMEM_BYTES>>>();
    routing_kernel<<<4096, 512>>>(b, out);
}

// round 5
// speedup vs baseline: 5.4189x; 1.4324x over previous
#include <cuda_runtime.h>
#include <cuda_fp16.h>
#include <cstdint>

// ---------------------------------------------------------------------------
// ConvCapsuleLayer3D via fp16 mma.sync m16n8k16 (f32 accumulate):
//   pad_kernel   : x -> g_xpad2, channel-pair-interleaved half2 padded volume
//                  [nb(8)][cihalf(8)][34][34][34] of half2(ch_even, ch_odd)
//   wfrag_kernel : W -> g_wfrag16, m16n8k16 A-fragments, K permuted by
//                  channel-pairing (pair q = (cihalf, tap))
//   conv_mma     : implicit GEMM, CTA = 128oc x 256pos, K=432 (216 pairs,
//                  27 k16-steps). Whole halo (32.6KB fp16) resident in smem.
//   routing      : fused 3-iter sigmoid routing, fp16 votes
// ---------------------------------------------------------------------------

#define KTOT 432
#define NQ   216       // k-pairs
#define PADC 39304     // 34^3
#define PADZ 1156
#define PADY 34

// halo strides (half2 units)
#define H_CI 1020      // 3*10*34
#define H_KD 340
#define H_KH 34

__device__ __half    g_votes[2 * 32768 * 1024];       // 134 MB
__device__ uint32_t  g_xpad2[8 * 8 * PADC];           // 10 MB  half2 pairs
__device__ uint4     g_wfrag16[27 * 16 * 32];         // 221 KB fragments

// conv smem: tbl[224] ints then halo[16320] uint32 (half2)
#define SM_HALO     224
#define SMEM_WORDS  (224 + 16320)
#define SMEM_BYTES  (SMEM_WORDS * 4)

// ---------------------------------------------------------------------------
// pad: X[(nb*16+ci)<<15 | pos] -> half2(ci even, ci odd) padded volume
// ---------------------------------------------------------------------------
__global__ void pad_kernel(const float* __restrict__ X) {
    int idx = blockIdx.x * 256 + threadIdx.x;
    if (idx >= 8 * 8 * PADC) return;
    int nb = idx / (8 * PADC);
    int r  = idx - nb * (8 * PADC);
    int ch2 = r / PADC;
    int pp  = r - ch2 * PADC;
    int zp = pp / PADZ;  pp -= zp * PADZ;
    int yp = pp / PADY;
    int xp = pp - yp * PADY;
    int z = zp - 1, y = yp - 1, x = xp - 1;
    float v0 = 0.f, v1 = 0.f;
    if ((unsigned)z < 32u && (unsigned)y < 32u && (unsigned)x < 32u) {
        int pos = (z << 10) + (y << 5) + x;
        const float* src = X + ((size_t)(nb * 16 + ch2 * 2) << 15) + pos;
        v0 = src[0];
        v1 = src[32768];
    }
    __half2 h = __floats2half2_rn(v0, v1);
    g_xpad2[idx] = *(uint32_t*)&h;
}

// ---------------------------------------------------------------------------
// wfrag: A fragments. i = ks*512 + m16*32 + lane ; 4 half2 per thread.
// pair q -> (cihalf = q/27, tap = q%27); k_even = 2*cihalf*27+tap, k_odd = +27
// ---------------------------------------------------------------------------
__global__ void wfrag_kernel(const float* __restrict__ W) {
    int i = blockIdx.x * 256 + threadIdx.x;
    if (i >= 27 * 16 * 32) return;
    int lane = i & 31;
    int m16  = (i >> 5) & 15;
    int ks   = i >> 9;
    int gid = lane >> 2, tig = lane & 3;
    uint32_t v[4];
    #pragma unroll
    for (int j = 0; j < 4; ++j) {
        int m = m16 * 16 + gid + ((j & 1) ? 8 : 0);
        int q = ks * 8 + tig + ((j >= 2) ? 4 : 0);
        int cihalf = q / 27;
        int tap    = q - cihalf * 27;
        int k0 = (2 * cihalf) * 27 + tap;
        __half2 h = __floats2half2_rn(W[m * KTOT + k0], W[m * KTOT + k0 + 27]);
        v[j] = *(uint32_t*)&h;
    }
    g_wfrag16[i] = make_uint4(v[0], v[1], v[2], v[3]);
}

// ---------------------------------------------------------------------------
// conv: grid (128 [z,y-quarter], 8 [nb], 2 [mt]), 512 threads
// warp tile 64oc x 32pos; 16 warps = (wm 2) x (wn 8); 27 k16-steps
// ---------------------------------------------------------------------------
__global__ void __launch_bounds__(512, 1)
conv_mma_kernel() {
    extern __shared__ uint32_t sm[];
    int*      tbl  = (int*)sm;
    uint32_t* halo = sm + SM_HALO;

    const int tid  = threadIdx.x;
    const int w    = tid >> 5, lane = tid & 31;
    const int gid  = lane >> 2, tig = lane & 3;
    const int wm   = w >> 3;
    const int wn   = w & 7;

    const int bx = blockIdx.x;
    const int nb = blockIdx.y;
    const int mt = blockIdx.z;
    const int z  = bx >> 2, y0 = (bx & 3) * 8;

    // pair-index -> halo offset table
    for (int q = tid; q < NQ; q += 512) {
        int cihalf = q / 27;
        int tap    = q - cihalf * 27;
        int kd = tap / 9;  int rr = tap - kd * 9;
        int kh = rr / 3;   int kw = rr - kh * 3;
        tbl[q] = cihalf * H_CI + kd * H_KD + kh * H_KH + kw;
    }
    // halo: 8 cihalf x zp[z..z+2] x yp[y0..y0+9] x xp[0..33]
    {
        const uint32_t* xsrc = g_xpad2 + nb * (8 * PADC) + z * PADZ + y0 * PADY;
        for (int i = tid; i < 16320; i += 512) {
            int row = i / 34;
            int x   = i - row * 34;
            int ch2 = row / 30;
            int rr  = row - ch2 * 30;
            int zp  = rr / 10;
            int yp  = rr - zp * 10;
            halo[ch2 * H_CI + zp * H_KD + yp * H_KH + x] =
                xsrc[ch2 * PADC + zp * PADZ + yp * PADY + x];
        }
    }
    __syncthreads();

    int posoff[4];
    #pragma unroll
    for (int nt = 0; nt < 4; ++nt) {
        int ncol = wn * 32 + nt * 8 + gid;
        posoff[nt] = (ncol >> 5) * H_KH + (ncol & 31);
    }

    float acc[4][4][4];
    #pragma unroll
    for (int a = 0; a < 4; ++a)
        #pragma unroll
        for (int b = 0; b < 4; ++b)
            #pragma unroll
            for (int c = 0; c < 4; ++c) acc[a][b][c] = 0.f;

    const uint4* wf = g_wfrag16 + (size_t)(mt * 8 + wm * 4) * 32 + lane;

    #pragma unroll 3
    for (int ks = 0; ks < 27; ++ks) {
        const int q0 = tbl[ks * 8 + tig];
        const int q1 = tbl[ks * 8 + tig + 4];
        uint4 A[4];
        #pragma unroll
        for (int mi = 0; mi < 4; ++mi)
            A[mi] = wf[(ks * 16 + mi) * 32];
        #pragma unroll
        for (int nt = 0; nt < 4; ++nt) {
            uint32_t b0 = halo[q0 + posoff[nt]];
            uint32_t b1 = halo[q1 + posoff[nt]];
            #pragma unroll
            for (int mi = 0; mi < 4; ++mi) {
                asm volatile(
                    "mma.sync.aligned.m16n8k16.row.col.f32.f16.f16.f32 "
                    "{%0,%1,%2,%3}, {%4,%5,%6,%7}, {%8,%9}, {%0,%1,%2,%3};"
                    : "+f"(acc[mi][nt][0]), "+f"(acc[mi][nt][1]),
                      "+f"(acc[mi][nt][2]), "+f"(acc[mi][nt][3])
                    : "r"(A[mi].x), "r"(A[mi].y), "r"(A[mi].z), "r"(A[mi].w),
                      "r"(b0), "r"(b1));
            }
        }
    }

    // epilogue: fp16 votes[b][p][ic*256+oc]
    const int b_ = nb >> 2, ic_ = nb & 3;
    #pragma unroll
    for (int mi = 0; mi < 4; ++mi) {
        const int oc = mt * 128 + wm * 64 + mi * 16 + gid;
        #pragma unroll
        for (int nt = 0; nt < 4; ++nt) {
            const int posl = wn * 32 + nt * 8 + tig * 2;
            const int y = y0 + (posl >> 5);
            const int x = posl & 31;
            const int p = (z << 10) | (y << 5) | x;
            __half* dst = g_votes + (((size_t)((b_ << 15) + p)) << 10)
                        + ic_ * 256 + oc;
            dst[0]        = __float2half_rn(acc[mi][nt][0]);
            dst[8]        = __float2half_rn(acc[mi][nt][2]);
            dst[1024]     = __float2half_rn(acc[mi][nt][1]);
            dst[1024 + 8] = __float2half_rn(acc[mi][nt][3]);
        }
    }
}

// ---------------------------------------------------------------------------
// routing: warp = position, lane = (nc, quarter), 8 atoms/lane, fp16 votes
// ---------------------------------------------------------------------------
__global__ void __launch_bounds__(512, 2)
routing_kernel(const float* __restrict__ bias, float* __restrict__ out) {
    __shared__ float s[256][17];

    const int lane = threadIdx.x & 31;
    const int warp = threadIdx.x >> 5;
    const int blk  = blockIdx.x;
    const int b    = blk >> 11;
    const int p0   = (blk & 2047) * 16;
    const int p    = p0 + warp;
    const int nc   = lane >> 2, q = lane & 3;

    const __half* vb = g_votes + (((size_t)((b << 15) + p)) << 10) + nc * 32 + q * 8;
    float v[4][8];
    #pragma unroll
    for (int ic = 0; ic < 4; ++ic) {
        uint4 raw = *(const uint4*)(vb + ic * 256);
        float2 f;
        f = __half22float2(*(__half2*)&raw.x); v[ic][0] = f.x; v[ic][1] = f.y;
        f = __half22float2(*(__half2*)&raw.y); v[ic][2] = f.x; v[ic][3] = f.y;
        f = __half22float2(*(__half2*)&raw.z); v[ic][4] = f.x; v[ic][5] = f.y;
        f = __half22float2(*(__half2*)&raw.w); v[ic][6] = f.x; v[ic][7] = f.y;
    }
    float bb[8];
    {
        float4 a = *(const float4*)(bias + nc * 32 + q * 8);
        float4 c = *(const float4*)(bias + nc * 32 + q * 8 + 4);
        bb[0] = a.x; bb[1] = a.y; bb[2] = a.z; bb[3] = a.w;
        bb[4] = c.x; bb[5] = c.y; bb[6] = c.z; bb[7] = c.w;
    }

    float lgt[4] = {1.f, 1.f, 1.f, 1.f};
    float act[8];

    #pragma unroll
    for (int it = 0; it < 3; ++it) {
        float r[4];
        #pragma unroll
        for (int ic = 0; ic < 4; ++ic)
            r[ic] = 1.0f / (1.0f + __expf(-lgt[ic]));

        float pre[8], sql = 0.f;
        #pragma unroll
        for (int j = 0; j < 8; ++j) {
            float pv = bb[j];
            #pragma unroll
            for (int ic = 0; ic < 4; ++ic) pv = fmaf(r[ic], v[ic][j], pv);
            pre[j] = pv;
            sql = fmaf(pv, pv, sql);
        }
        sql += __shfl_xor_sync(0xFFFFFFFFu, sql, 1);
        sql += __shfl_xor_sync(0xFFFFFFFFu, sql, 2);
        float scale = sql / ((1.0f + sql) * sqrtf(sql + 1e-9f));
        #pragma unroll
        for (int j = 0; j < 8; ++j) act[j] = pre[j] * scale;

        if (it < 2) {
            #pragma unroll
            for (int ic = 0; ic < 4; ++ic) {
                float d = 0.f;
                #pragma unroll
                for (int j = 0; j < 8; ++j) d = fmaf(v[ic][j], act[j], d);
                d += __shfl_xor_sync(0xFFFFFFFFu, d, 1);
                d += __shfl_xor_sync(0xFFFFFFFFu, d, 2);
                lgt[ic] += d;
            }
        }
    }

    #pragma unroll
    for (int j = 0; j < 8; ++j) s[nc * 32 + q * 8 + j][warp] = act[j];
    __syncthreads();

    const int c  = threadIdx.x & 15;
    const int rw = threadIdx.x >> 4;
    #pragma unroll
    for (int rr = 0; rr < 8; ++rr) {
        int row = rr * 32 + rw;
        out[((size_t)(b * 256 + row) << 15) + p0 + c] = s[row][c];
    }
}

// ---------------------------------------------------------------------------
extern "C" void kernel_launch(void* const* d_in, const int* in_sizes, int n_in,
                              void* d_out, int out_size) {
    const float* x = (const float*)d_in[0];
    const float* W = (const float*)d_in[1];
    const float* b = (const float*)d_in[2];
    float* out = (float*)d_out;

    cudaFuncSetAttribute(conv_mma_kernel,
                         cudaFuncAttributeMaxDynamicSharedMemorySize, SMEM_BYTES);

    pad_kernel<<<(8 * 8 * PADC + 255) / 256, 256>>>(x);
    wfrag_kernel<<<(27 * 16 * 32 + 255) / 256, 256>>>(W);
    dim3 cgrid(128, 8, 2);
    conv_mma_kernel<<<cgrid, 512, SMEM_BYTES>>>();
    routing_kernel<<<4096, 512>>>(b, out);
}